// round 1
// baseline (speedup 1.0000x reference)
#include <cuda_runtime.h>
#include <cstdint>

#define BB   16
#define CC   32
#define HH   256
#define WW   256
#define T2   8
#define CH   16
#define NCH  (HH/CH)          // 16 chunks
#define FIELD (HH*WW)         // 65536
#define TPC  2                // trees per CTA in k1

typedef unsigned long long u64;

// ---------------- scratch (no cudaMalloc allowed) ----------------
__device__ __align__(256) float g_w1 [BB*T2*FIELD];
__device__ __align__(256) float g_w2 [BB*T2*FIELD];
__device__ __align__(256) float g_w1p[BB*T2*FIELD];
__device__ __align__(256) float g_g3 [BB*T2*FIELD];
__device__ __align__(256) float g_g3p[BB*T2*FIELD];
__device__ __align__(256) float g_g2p[BB*T2*FIELD];
__device__ __align__(256) float g_gv2[BB*T2*FIELD];
__device__ __align__(256) float g_S  [BB*T2*4*NCH*WW];   // [b][t][f:4][chunk][w]

// ---------------- f32x2 helpers ----------------
__device__ __forceinline__ u64 fma2(u64 a, u64 b, u64 c) {
    u64 d;
    asm("fma.rn.f32x2 %0, %1, %2, %3;" : "=l"(d) : "l"(a), "l"(b), "l"(c));
    return d;
}
__device__ __forceinline__ u64 pack2(float lo, float hi) {
    u64 r;
    asm("mov.b64 %0, {%1, %2};" : "=l"(r) : "f"(lo), "f"(hi));
    return r;
}
__device__ __forceinline__ float2 unpack2(u64 v) {
    float2 f;
    asm("mov.b64 {%0, %1}, %2;" : "=f"(f.x), "=f"(f.y) : "l"(v));
    return f;
}

// ---------------- 4-warp (128-lane, 256-element) scan ----------------
// Each lane holds elements (2*lt, 2*lt+1). Returns inclusive prefix for both
// elements and the total. Uses CTA-wide __syncthreads (all callers invoke it
// uniformly from every thread in the block).
__device__ __forceinline__ void scan256(float v0, float v1, float* ws4,
                                        int lane, int w4,
                                        float& incl0, float& incl1, float& tot)
{
    float pair = v0 + v1;
    float s = pair;
    #pragma unroll
    for (int d = 1; d < 32; d <<= 1) {
        float n = __shfl_up_sync(0xffffffffu, s, d);
        if (lane >= d) s += n;
    }
    if (lane == 31) ws4[w4] = s;
    __syncthreads();
    float off = 0.f, t_ = 0.f;
    #pragma unroll
    for (int j = 0; j < 4; j++) {
        float w_ = ws4[j];
        t_ += w_;
        if (j < w4) off += w_;
    }
    __syncthreads();
    float excl_pair = off + (s - pair);
    incl0 = excl_pair + v0;
    incl1 = incl0 + v1;
    tot   = t_;
}

// =====================================================================
// K1: weighted fields + row scans + per-chunk column sums
// grid = (T2/TPC, NCH, BB), block = 256 (2 row-halves x 128 lanes, 2 cols/lane)
// =====================================================================
__global__ void __launch_bounds__(256) k1_weight(
    const float* __restrict__ x,
    const float* __restrict__ a1,  const float* __restrict__ a2,
    const float* __restrict__ a3,  const float* __restrict__ a1p,
    const float* __restrict__ a2p, const float* __restrict__ a3p)
{
    __shared__ u64   s_alpha[TPC][6][CC];
    __shared__ float s_ws[2][4];
    __shared__ float s_cs[2][TPC][3][WW];   // per-half column partials (g3,g3p,g2p)

    const int tid   = threadIdx.x;
    const int half  = tid >> 7;       // which 8-row sub-chunk
    const int lt    = tid & 127;      // column pair index
    const int lane  = lt & 31;
    const int w4    = lt >> 5;
    const int t0    = blockIdx.x * TPC;
    const int chunk = blockIdx.y;
    const int b     = blockIdx.z;

    {
        const float* aptr[6] = {a1, a2, a3, a1p, a2p, a3p};
        for (int i = tid; i < TPC * 6 * CC; i += 256) {
            int tr = i / (6 * CC);
            int f  = (i / CC) % 6;
            int c  = i % CC;
            float v = aptr[f][(t0 + tr) * CC + c];
            s_alpha[tr][f][c] = pack2(v, v);
        }
        for (int i = tid; i < 2 * TPC * 3 * WW; i += 256)
            ((float*)s_cs)[i] = 0.f;
    }
    __syncthreads();

    const int hbase = chunk * CH + half * 8;

    #pragma unroll 1
    for (int i0 = 0; i0 < 8; i0 += 2) {
        const int h = hbase + i0;
        u64 acc[2][TPC][6];
        #pragma unroll
        for (int r = 0; r < 2; r++)
            #pragma unroll
            for (int tr = 0; tr < TPC; tr++)
                #pragma unroll
                for (int f = 0; f < 6; f++)
                    acc[r][tr][f] = 0ull;

        const u64* xp = (const u64*)(x + (size_t)b * CC * FIELD + (size_t)h * WW) + lt;
        #pragma unroll
        for (int c = 0; c < CC; c++) {
            u64 x0 = xp[(size_t)c * (FIELD / 2)];
            u64 x1 = xp[(size_t)c * (FIELD / 2) + (WW / 2)];
            #pragma unroll
            for (int tr = 0; tr < TPC; tr++)
                #pragma unroll
                for (int f = 0; f < 6; f++) {
                    u64 al = s_alpha[tr][f][c];
                    acc[0][tr][f] = fma2(x0, al, acc[0][tr][f]);
                    acc[1][tr][f] = fma2(x1, al, acc[1][tr][f]);
                }
        }

        #pragma unroll
        for (int r = 0; r < 2; r++) {
            const int hh = h + r;
            #pragma unroll
            for (int tr = 0; tr < TPC; tr++) {
                float2 w1v  = unpack2(acc[r][tr][0]);
                float2 w2v  = unpack2(acc[r][tr][1]);
                float2 w3v  = unpack2(acc[r][tr][2]);
                float2 w1pv = unpack2(acc[r][tr][3]);
                float2 w2pv = unpack2(acc[r][tr][4]);
                float2 w3pv = unpack2(acc[r][tr][5]);

                float i0_, i1_, tot;
                // g3 = strict forward prefix of w3 along w
                scan256(w3v.x, w3v.y, s_ws[half], lane, w4, i0_, i1_, tot);
                float g3a = i0_ - w3v.x, g3b = i1_ - w3v.y;
                // g3p = strict forward prefix of w3p
                scan256(w3pv.x, w3pv.y, s_ws[half], lane, w4, i0_, i1_, tot);
                float g3pa = i0_ - w3pv.x, g3pb = i1_ - w3pv.y;
                // g2p = strict reverse prefix of w2p
                scan256(w2pv.x, w2pv.y, s_ws[half], lane, w4, i0_, i1_, tot);
                float g2pa = tot - i0_, g2pb = tot - i1_;

                size_t base = ((size_t)(b * T2 + t0 + tr) * HH + hh) * WW + 2 * lt;
                *(float2*)&g_w1 [base] = w1v;
                *(float2*)&g_w2 [base] = w2v;
                *(float2*)&g_w1p[base] = w1pv;
                *(float2*)&g_g3 [base] = make_float2(g3a,  g3b);
                *(float2*)&g_g3p[base] = make_float2(g3pa, g3pb);
                *(float2*)&g_g2p[base] = make_float2(g2pa, g2pb);

                s_cs[half][tr][0][2*lt]   += g3a;
                s_cs[half][tr][0][2*lt+1] += g3b;
                s_cs[half][tr][1][2*lt]   += g3pa;
                s_cs[half][tr][1][2*lt+1] += g3pb;
                s_cs[half][tr][2][2*lt]   += g2pa;
                s_cs[half][tr][2][2*lt+1] += g2pb;
            }
        }
    }
    __syncthreads();

    for (int i = tid; i < TPC * 3 * WW; i += 256) {
        int tr = i / (3 * WW);
        int f  = (i / WW) % 3;
        int w  = i % WW;
        float v = s_cs[0][tr][f][w] + s_cs[1][tr][f][w];
        g_S[((((size_t)b * T2 + t0 + tr) * 4 + f) * NCH + chunk) * WW + w] = v;
    }
}

// =====================================================================
// K2: bottom-up pass. v2 = w2 * SW(w3); gv2 = rev-excl-w-scan(v2);
//     cherry = w1p * SW(w3p) * SE(w2p)   (written straight to output)
// grid = (NCH, T2, BB), block = 128 (2 cols/lane)
// =====================================================================
__global__ void __launch_bounds__(128) k2_bottomup(float* __restrict__ out)
{
    __shared__ float s_ws[4];
    const int lt    = threadIdx.x;
    const int lane  = lt & 31;
    const int w4    = lt >> 5;
    const int chunk = blockIdx.x;
    const int t     = blockIdx.y;
    const int b     = blockIdx.z;

    const size_t Sbase = ((size_t)b * T2 + t) * 4 * NCH * WW;
    float a3a = 0, a3b = 0, p3a = 0, p3b = 0, p2a = 0, p2b = 0;
    for (int j = chunk + 1; j < NCH; j++) {
        size_t o = (size_t)j * WW + 2 * lt;
        a3a += g_S[Sbase + 0*NCH*WW + o];  a3b += g_S[Sbase + 0*NCH*WW + o + 1];
        p3a += g_S[Sbase + 1*NCH*WW + o];  p3b += g_S[Sbase + 1*NCH*WW + o + 1];
        p2a += g_S[Sbase + 2*NCH*WW + o];  p2b += g_S[Sbase + 2*NCH*WW + o + 1];
    }

    const size_t fbase = ((size_t)b * T2 + t) * FIELD;
    const size_t obase = ((size_t)b * 16 + 8 + t) * FIELD;   // cherry half of output
    float csa = 0, csb = 0;

    #pragma unroll 1
    for (int r = CH - 1; r >= 0; r--) {
        const int h = chunk * CH + r;
        const size_t idx = fbase + (size_t)h * WW + 2 * lt;
        float2 w2v  = *(const float2*)&g_w2 [idx];
        float2 g3v  = *(const float2*)&g_g3 [idx];
        float2 g3pv = *(const float2*)&g_g3p[idx];
        float2 g2pv = *(const float2*)&g_g2p[idx];
        float2 w1pv = *(const float2*)&g_w1p[idx];

        float v2a = w2v.x * a3a;
        float v2b = w2v.y * a3b;
        float i0_, i1_, tot;
        scan256(v2a, v2b, s_ws, lane, w4, i0_, i1_, tot);
        float gva = tot - i0_;              // strict reverse prefix along w
        float gvb = tot - i1_;
        *(float2*)&g_gv2[idx] = make_float2(gva, gvb);
        csa += gva; csb += gvb;

        *(float2*)&out[obase + (size_t)h * WW + 2 * lt] =
            make_float2(w1pv.x * p3a * p2a, w1pv.y * p3b * p2b);

        a3a += g3v.x;  a3b += g3v.y;
        p3a += g3pv.x; p3b += g3pv.y;
        p2a += g2pv.x; p2b += g2pv.y;
    }

    g_S[Sbase + 3*NCH*WW + (size_t)chunk * WW + 2*lt]     = csa;
    g_S[Sbase + 3*NCH*WW + (size_t)chunk * WW + 2*lt + 1] = csb;
}

// =====================================================================
// K3: top-down pass. linear = w1 * NE(v2) = w1 * column-prefix(gv2)
// grid = (NCH, T2, BB), block = 128
// =====================================================================
__global__ void __launch_bounds__(128) k3_topdown(float* __restrict__ out)
{
    const int lt    = threadIdx.x;
    const int chunk = blockIdx.x;
    const int t     = blockIdx.y;
    const int b     = blockIdx.z;

    const size_t Sbase = ((size_t)b * T2 + t) * 4 * NCH * WW + 3 * NCH * WW;
    float va = 0, vb = 0;
    for (int j = 0; j < chunk; j++) {
        va += g_S[Sbase + (size_t)j * WW + 2 * lt];
        vb += g_S[Sbase + (size_t)j * WW + 2 * lt + 1];
    }

    const size_t fbase = ((size_t)b * T2 + t) * FIELD;
    const size_t obase = ((size_t)b * 16 + t) * FIELD;       // linear half of output

    #pragma unroll 1
    for (int r = 0; r < CH; r++) {
        const int h = chunk * CH + r;
        const size_t idx = fbase + (size_t)h * WW + 2 * lt;
        float2 w1v = *(const float2*)&g_w1 [idx];
        float2 gv  = *(const float2*)&g_gv2[idx];
        *(float2*)&out[obase + (size_t)h * WW + 2 * lt] =
            make_float2(w1v.x * va, w1v.y * vb);
        va += gv.x;
        vb += gv.y;
    }
}

// =====================================================================
extern "C" void kernel_launch(void* const* d_in, const int* in_sizes, int n_in,
                              void* d_out, int out_size)
{
    const float* x   = (const float*)d_in[0];
    const float* a1  = (const float*)d_in[1];
    const float* a2  = (const float*)d_in[2];
    const float* a3  = (const float*)d_in[3];
    const float* a1p = (const float*)d_in[4];
    const float* a2p = (const float*)d_in[5];
    const float* a3p = (const float*)d_in[6];
    float* out = (float*)d_out;

    dim3 g1(T2 / TPC, NCH, BB);     // (4, 16, 16)
    dim3 g2(NCH, T2, BB);           // (16, 8, 16)

    k1_weight<<<g1, 256>>>(x, a1, a2, a3, a1p, a2p, a3p);
    k2_bottomup<<<g2, 128>>>(out);
    k3_topdown<<<g2, 128>>>(out);
}